// round 15
// baseline (speedup 1.0000x reference)
#include <cuda_runtime.h>
#include <cuda_bf16.h>
#include <cuda_fp16.h>
#include <math.h>
#include <stdint.h>

#define Bn 2
#define Tn 2048
#define Cn 1024
#define Hn 16
#define Dn 64
#define Mn (Bn*Tn)          // 4096
#define BHn (Bn*Hn)         // 32

typedef unsigned long long ull;

// ---------------- device scratch ----------------
__device__ __half         g_Qh[BHn*Tn*Dn];  // head-major, pre-scaled by 0.125*log2e
__device__ __half         g_Kh[BHn*Tn*Dn];  // fp16 hi only
__device__ float          g_V [BHn*Tn*Dn];  // raw v (fp32) -- only for p!=1 channels
__device__ __nv_bfloat16  g_Vh[BHn*Tn*Dn];  // transformed V bf16 hi/lo
__device__ __nv_bfloat16  g_Vl[BHn*Tn*Dn];
__device__ float g_zmax[Bn*Cn];
__device__ float g_zpmax[16*Bn*Cn];         // partial wmax (p!=1 only)
__device__ float g_zpmin[16*Bn*Cn];         // partial wmin (p!=1 only)
__device__ __half gA_hi[Mn*Cn];             // fp16 A operand (x conv, then Y from FA)
__device__ __half gBT_hi[3*Cn*Cn];          // fp16 w_attn^T
__device__ __half gBT2  [Cn*Cn];            // fp16 w_proj^T

#define QSCALE 0.18033688f   // 0.125 * log2(e)

__device__ __forceinline__ float clamp_p(float pp) {
    float sgn = (pp >= 0.0f) ? 1.0f : -1.0f;
    return sgn * fminf(fmaxf(fabsf(pp), 1e-4f), 1e3f);
}

// ---------------- ptx helpers ----------------
__device__ __forceinline__ uint32_t smem_u32(const void* p) {
    uint32_t a;
    asm("{ .reg .u64 t; cvta.to.shared.u64 t, %1; cvt.u32.u64 %0, t; }" : "=r"(a) : "l"(p));
    return a;
}
__device__ __forceinline__ void cp16(uint32_t dst, const void* src) {
    asm volatile("cp.async.cg.shared.global [%0], [%1], 16;\n" :: "r"(dst), "l"(src));
}
#define CP_COMMIT() asm volatile("cp.async.commit_group;\n" ::: "memory")

__device__ __forceinline__ void ldsm4(uint32_t& r0, uint32_t& r1, uint32_t& r2, uint32_t& r3,
                                      uint32_t addr) {
    asm volatile("ldmatrix.sync.aligned.m8n8.x4.shared.b16 {%0,%1,%2,%3}, [%4];"
                 : "=r"(r0), "=r"(r1), "=r"(r2), "=r"(r3) : "r"(addr));
}
__device__ __forceinline__ void ldsm4t(uint32_t& r0, uint32_t& r1, uint32_t& r2, uint32_t& r3,
                                       uint32_t addr) {
    asm volatile("ldmatrix.sync.aligned.m8n8.x4.trans.shared.b16 {%0,%1,%2,%3}, [%4];"
                 : "=r"(r0), "=r"(r1), "=r"(r2), "=r"(r3) : "r"(addr));
}
__device__ __forceinline__ void mma16816(float* c, const uint32_t* a, const uint32_t* b) {
    asm volatile(
        "mma.sync.aligned.m16n8k16.row.col.f32.bf16.bf16.f32 "
        "{%0,%1,%2,%3}, {%4,%5,%6,%7}, {%8,%9}, {%0,%1,%2,%3};"
        : "+f"(c[0]), "+f"(c[1]), "+f"(c[2]), "+f"(c[3])
        : "r"(a[0]), "r"(a[1]), "r"(a[2]), "r"(a[3]), "r"(b[0]), "r"(b[1]));
}
__device__ __forceinline__ void mma16816h(float* c, const uint32_t* a, const uint32_t* b) {
    asm volatile(
        "mma.sync.aligned.m16n8k16.row.col.f32.f16.f16.f32 "
        "{%0,%1,%2,%3}, {%4,%5,%6,%7}, {%8,%9}, {%0,%1,%2,%3};"
        : "+f"(c[0]), "+f"(c[1]), "+f"(c[2]), "+f"(c[3])
        : "r"(a[0]), "r"(a[1]), "r"(a[2]), "r"(a[3]), "r"(b[0]), "r"(b[1]));
}
__device__ __forceinline__ uint32_t pkbf(float lo, float hi) {
    uint32_t r;
    asm("cvt.rn.bf16x2.f32 %0, %1, %2;" : "=r"(r) : "f"(hi), "f"(lo));
    return r;
}
__device__ __forceinline__ uint32_t pkhf(float lo, float hi) {
    uint32_t r;
    asm("cvt.rn.f16x2.f32 %0, %1, %2;" : "=r"(r) : "f"(hi), "f"(lo));
    return r;
}
__device__ __forceinline__ void bfsplit(float a, float b, uint32_t& hi, uint32_t& lo) {
    hi = pkbf(a, b);
    float f0 = __uint_as_float(hi << 16);
    float f1 = __uint_as_float(hi & 0xffff0000u);
    lo = pkbf(a - f0, b - f1);
}

// ---------------------------------------------------------------------------
// mega prep: [0,4096) conv x->fp16; [4096,7168) transpose w_attn;
// [7168,8192) transpose w_proj.
// ---------------------------------------------------------------------------
__global__ __launch_bounds__(256) void prep_kernel(
    const float* __restrict__ x,
    const float* __restrict__ w_attn,
    const float* __restrict__ w_proj)
{
    __shared__ float tile[32][33];
    int bid = blockIdx.x;
    int tid = threadIdx.x;
    if (bid < 4096) {
        int i = bid * 256 + tid;
        float4 a = ((const float4*)x)[i];
        ((uint2*)gA_hi)[i] = make_uint2(pkhf(a.x, a.y), pkhf(a.z, a.w));
        return;
    }
    const float* W;
    __half* Th;
    int Nd, bx, by;
    if (bid < 7168) {
        int t = bid - 4096;
        W = w_attn; Th = gBT_hi; Nd = 3072;
        bx = t % 96; by = t / 96;
    } else {
        int t = bid - 7168;
        W = w_proj; Th = gBT2; Nd = 1024;
        bx = t % 32; by = t / 32;
    }
    int nx = bx * 32, kx = by * 32;
    int tx = tid & 31, ty = tid >> 5;
#pragma unroll
    for (int r = ty; r < 32; r += 8)
        tile[r][tx] = W[(size_t)(kx + r) * Nd + nx + tx];
    __syncthreads();
#pragma unroll
    for (int r = ty; r < 32; r += 8) {
        size_t o = (size_t)(nx + r) * 1024 + kx + tx;
        Th[o] = __float2half_rn(tile[tx][r]);
    }
}

// ---------------------------------------------------------------------------
// fp16 single-term mma.sync GEMM: CTA 128x128, warp tile 64x32 (2x4 warps),
// BK=64, cp.async double buffer, 64 KB smem.
// ---------------------------------------------------------------------------
#define G_BHI 16384
#define G_STG 32768
#define TCG_SMEM (2*G_STG)   // 64 KB

__device__ __forceinline__ void load_stage(
    uint32_t sbase,
    const __half* __restrict__ Ah, const __half* __restrict__ Bh,
    int m0, int n0, int k0, int tid)
{
#pragma unroll
    for (int j = 0; j < 4; j++) {
        int idx = tid + j * 256;
        int row = idx >> 3, c = idx & 7;
        uint32_t sw = row * 128 + ((c ^ (row & 7)) << 4);
        size_t ga = (size_t)(m0 + row) * 1024 + k0 + c * 8;
        cp16(sbase + sw, Ah + ga);
    }
#pragma unroll
    for (int j = 0; j < 4; j++) {
        int idx = tid + j * 256;
        int row = idx >> 3, c = idx & 7;
        uint32_t sw = row * 128 + ((c ^ (row & 7)) << 4);
        size_t gb = (size_t)(n0 + row) * 1024 + k0 + c * 8;
        cp16(sbase + G_BHI + sw, Bh + gb);
    }
}

template<int MODE>
__global__ __launch_bounds__(256, 2) void tc_gemm(
    const __half* __restrict__ Ah, const __half* __restrict__ Bh,
    const float* __restrict__ bias, float* __restrict__ Cout,
    const float* __restrict__ p_param)
{
    extern __shared__ char smem[];
    uint32_t sb = smem_u32(smem);
    const int tid  = threadIdx.x;
    const int wid  = tid >> 5;
    const int lane = tid & 31;
    const int wm = wid & 1;
    const int wn = wid >> 1;
    const int m0 = blockIdx.y * 128;
    const int n0 = blockIdx.x * 128;

    float acc[4][4][4];
#pragma unroll
    for (int i = 0; i < 4; i++)
#pragma unroll
        for (int j = 0; j < 4; j++)
#pragma unroll
            for (int q = 0; q < 4; q++) acc[i][j][q] = 0.0f;

    load_stage(sb,         Ah, Bh, m0, n0, 0,  tid); CP_COMMIT();
    load_stage(sb + G_STG, Ah, Bh, m0, n0, 64, tid); CP_COMMIT();

    const int a_row = wm * 64 + (lane & 15);
    const int a_c16 = (lane >> 4);
    const int b_row = wn * 32 + ((lane >> 4) << 3) + (lane & 7);
    const int b_cof = ((lane >> 3) & 1);

    for (int it = 0; it < 16; it++) {
        const int s = it & 1;
        const uint32_t sbase = sb + s * G_STG;
        if (it < 15) asm volatile("cp.async.wait_group 1;\n" ::: "memory");
        else         asm volatile("cp.async.wait_group 0;\n" ::: "memory");
        __syncthreads();

#pragma unroll
        for (int ks = 0; ks < 4; ks++) {
            uint32_t ahi[4][4];
#pragma unroll
            for (int mf = 0; mf < 4; mf++) {
                int row = a_row + mf * 16;
                int c16 = ks * 2 + a_c16;
                uint32_t ad = sbase + row * 128 + ((c16 ^ (row & 7)) << 4);
                ldsm4(ahi[mf][0], ahi[mf][1], ahi[mf][2], ahi[mf][3], ad);
            }
#pragma unroll
            for (int nf2 = 0; nf2 < 2; nf2++) {
                int row = b_row + nf2 * 16;
                int c16 = ks * 2 + b_cof;
                uint32_t bd = sbase + G_BHI + row * 128 + ((c16 ^ (row & 7)) << 4);
                uint32_t bh4[4];
                ldsm4(bh4[0], bh4[1], bh4[2], bh4[3], bd);
#pragma unroll
                for (int mf = 0; mf < 4; mf++) {
                    mma16816h(acc[mf][2*nf2],   ahi[mf], bh4);
                    mma16816h(acc[mf][2*nf2+1], ahi[mf], bh4 + 2);
                }
            }
        }
        __syncthreads();
        if (it + 2 < 16) {
            load_stage(sbase, Ah, Bh, m0, n0, (it + 2) * 64, tid);
            CP_COMMIT();
        }
    }

    const int mbase = m0 + wm * 64 + (lane >> 2);
    const int nbase = n0 + wn * 32 + (lane & 3) * 2;
    const int sec = n0 >> 10;
    float pp0[4], pp1[4];
    if (MODE == 1 && sec == 2) {
#pragma unroll
        for (int nf = 0; nf < 4; nf++) {
            int c1 = (nbase + nf * 8) & 1023;
            pp0[nf] = clamp_p(p_param[c1]);
            pp1[nf] = clamp_p(p_param[c1 + 1]);
        }
    }
#pragma unroll
    for (int mf = 0; mf < 4; mf++) {
#pragma unroll
        for (int half = 0; half < 2; half++) {
            int m = mbase + mf * 16 + half * 8;
#pragma unroll
            for (int nf = 0; nf < 4; nf++) {
                int n = nbase + nf * 8;
                float v0 = acc[mf][nf][half*2+0] + bias[n];
                float v1 = acc[mf][nf][half*2+1] + bias[n+1];
                if (MODE == 0) {
                    *(float2*)(Cout + (size_t)m * Cn + n) = make_float2(v0, v1);
                } else {
                    int c1  = n & 1023;
                    int h   = c1 >> 6, dd = c1 & 63;
                    int bq  = m >> 11, t = m & 2047;
                    size_t idx = ((size_t)((bq * Hn + h) * Tn + t)) * 64 + dd;
                    if (sec == 2) {
                        if (pp0[nf] == 1.0f && pp1[nf] == 1.0f) {
                            float w0 = fmaxf(fabsf(v0 + 5.0f), 1e-10f);
                            float w1 = fmaxf(fabsf(v1 + 5.0f), 1e-10f);
                            uint32_t hh, ll;
                            bfsplit(w0, w1, hh, ll);
                            ((uint32_t*)g_Vh)[idx >> 1] = hh;
                            ((uint32_t*)g_Vl)[idx >> 1] = ll;
                        } else {
                            *(float2*)(g_V + idx) = make_float2(v0, v1);
                        }
                    } else if (sec == 1) {
                        *(uint32_t*)(g_Kh + idx) = pkhf(v0, v1);
                    } else {
                        *(uint32_t*)(g_Qh + idx) = pkhf(v0 * QSCALE, v1 * QSCALE);
                    }
                }
            }
        }
    }
}

// ---------------------------------------------------------------------------
// w-range partial: only for channels with p != 1
// ---------------------------------------------------------------------------
__global__ __launch_bounds__(256) void zmax_part(const float* __restrict__ p_param)
{
    int bh = blockIdx.x, chunk = blockIdx.y;
    int b = bh >> 4, h = bh & 15;
    int d4 = threadIdx.x & 15;
    int g  = threadIdx.x >> 4;
    int c  = h*64 + d4*4;

    bool need = (clamp_p(p_param[c+0]) != 1.0f) || (clamp_p(p_param[c+1]) != 1.0f) ||
                (clamp_p(p_param[c+2]) != 1.0f) || (clamp_p(p_param[c+3]) != 1.0f);

    float4 mx = make_float4(-1e30f, -1e30f, -1e30f, -1e30f);
    float4 mn = make_float4( 1e30f,  1e30f,  1e30f,  1e30f);
    if (need) {
        const float* vp = g_V + (size_t)bh * Tn * 64;
        for (int t = chunk*128 + g; t < (chunk+1)*128; t += 16) {
            float4 v = *(const float4*)(vp + t*64 + d4*4);
            float w0 = fmaxf(fabsf(v.x + 5.0f), 1e-10f);
            float w1 = fmaxf(fabsf(v.y + 5.0f), 1e-10f);
            float w2 = fmaxf(fabsf(v.z + 5.0f), 1e-10f);
            float w3 = fmaxf(fabsf(v.w + 5.0f), 1e-10f);
            mx.x = fmaxf(mx.x, w0); mn.x = fminf(mn.x, w0);
            mx.y = fmaxf(mx.y, w1); mn.y = fminf(mn.y, w1);
            mx.z = fmaxf(mx.z, w2); mn.z = fminf(mn.z, w2);
            mx.w = fmaxf(mx.w, w3); mn.w = fminf(mn.w, w3);
        }
    }
    __shared__ float4 redx[256];
    __shared__ float4 redn[256];
    redx[threadIdx.x] = mx;
    redn[threadIdx.x] = mn;
    __syncthreads();
    if (threadIdx.x < 16) {
        float4 m = redx[threadIdx.x];
        float4 q = redn[threadIdx.x];
#pragma unroll
        for (int gg = 1; gg < 16; gg++) {
            float4 o = redx[gg*16 + threadIdx.x];
            float4 u = redn[gg*16 + threadIdx.x];
            m.x = fmaxf(m.x, o.x); m.y = fmaxf(m.y, o.y);
            m.z = fmaxf(m.z, o.z); m.w = fmaxf(m.w, o.w);
            q.x = fminf(q.x, u.x); q.y = fminf(q.y, u.y);
            q.z = fminf(q.z, u.z); q.w = fminf(q.w, u.w);
        }
        int off = chunk*(Bn*Cn) + b*Cn + h*64 + threadIdx.x*4;
        *(float4*)(g_zpmax + off) = m;
        *(float4*)(g_zpmin + off) = q;
    }
}

// ---------------------------------------------------------------------------
// V transform fixup + inline zmax reduce: only for p != 1 channels.
// Block 0 additionally publishes g_zmax for the FA epilogue.
// ---------------------------------------------------------------------------
__device__ __forceinline__ float reduce_zmax(int i, float p) {
    float wmax = -1e30f, wmin = 1e30f;
#pragma unroll
    for (int ch = 0; ch < 16; ch++) {
        wmax = fmaxf(wmax, g_zpmax[ch*(Bn*Cn) + i]);
        wmin = fminf(wmin, g_zpmin[ch*(Bn*Cn) + i]);
    }
    return (p >= 0.0f) ? p * __logf(wmax) : p * __logf(wmin);
}

__global__ __launch_bounds__(256) void vexp_kernel(const float* __restrict__ p_param)
{
    int i = blockIdx.x * 256 + threadIdx.x;
    int base = i * 4;
    int dd = base & 63;
    int bh = base >> 17;
    int h = bh & 15, b = bh >> 4;
    int c = h*64 + dd;
    float p0 = clamp_p(p_param[c+0]), p1 = clamp_p(p_param[c+1]);
    float p2 = clamp_p(p_param[c+2]), p3 = clamp_p(p_param[c+3]);
    bool f01 = (p0 == 1.0f) && (p1 == 1.0f);
    bool f23 = (p2 == 1.0f) && (p3 == 1.0f);
    // publish g_zmax once (first 2048 threads cover all (b,c))
    if (blockIdx.x < 8) {
        int gi = blockIdx.x * 256 + threadIdx.x;   // 0..2047
        float pg = clamp_p(p_param[gi & (Cn-1)]);
        g_zmax[gi] = (pg == 1.0f) ? 0.0f : reduce_zmax(gi, pg);
    }
    if (f01 && f23) return;
    if (!f01) {
        float zm0 = (p0 == 1.0f) ? 0.0f : reduce_zmax(b*Cn + c,     p0);
        float zm1 = (p1 == 1.0f) ? 0.0f : reduce_zmax(b*Cn + c + 1, p1);
        float2 v = *(const float2*)(g_V + base);
        float w0 = fmaxf(fabsf(v.x + 5.0f), 1e-10f);
        float w1 = fmaxf(fabsf(v.y + 5.0f), 1e-10f);
        float e0 = (p0 == 1.0f) ? w0 : __expf(p0 * __logf(w0) - zm0);
        float e1 = (p1 == 1.0f) ? w1 : __expf(p1 * __logf(w1) - zm1);
        uint32_t hh, ll;
        bfsplit(e0, e1, hh, ll);
        ((uint32_t*)g_Vh)[base >> 1] = hh;
        ((uint32_t*)g_Vl)[base >> 1] = ll;
    }
    if (!f23) {
        float zm2 = (p2 == 1.0f) ? 0.0f : reduce_zmax(b*Cn + c + 2, p2);
        float zm3 = (p3 == 1.0f) ? 0.0f : reduce_zmax(b*Cn + c + 3, p3);
        float2 v = *(const float2*)(g_V + base + 2);
        float w0 = fmaxf(fabsf(v.x + 5.0f), 1e-10f);
        float w1 = fmaxf(fabsf(v.y + 5.0f), 1e-10f);
        float e0 = (p2 == 1.0f) ? w0 : __expf(p2 * __logf(w0) - zm2);
        float e1 = (p3 == 1.0f) ? w1 : __expf(p3 * __logf(w1) - zm3);
        uint32_t hh, ll;
        bfsplit(e0, e1, hh, ll);
        ((uint32_t*)g_Vh)[(base + 2) >> 1] = hh;
        ((uint32_t*)g_Vl)[(base + 2) >> 1] = ll;
    }
}

// ---------------------------------------------------------------------------
// Tensor-core flash attention (causal), BQ=BK=64, 4 warps, 56 KB smem,
// 3 CTAs/SM. S in log2 domain (Q pre-scaled by 0.125*log2e), exp2f softmax.
// S = fp16 1-term Qh·Kh; P·V bf16 3-term. p==1: y = mean - 5.
// ---------------------------------------------------------------------------
#define FAQ_H 0
#define FASTG0 8192
#define FASTG_SZ 24576
#define FKH 0
#define FVH 8192
#define FVL 16384
#define FA_SMEM (8192 + 2*FASTG_SZ)   // 56 KB

__device__ __forceinline__ void fa_load_stage(uint32_t sbase, int bh, int kt, int tid)
{
    const char* srcs[3] = {(const char*)g_Kh, (const char*)g_Vh, (const char*)g_Vl};
#pragma unroll
    for (int j = 0; j < 12; j++) {
        int idx = tid + j * 128;
        int arr = idx >> 9;
        int rem = idx & 511;
        int row = rem >> 3, c = rem & 7;
        uint32_t sw = arr * 8192 + row * 128 + ((c ^ (row & 7)) << 4);
        size_t gb = (((size_t)bh * Tn + kt * 64 + row) * 64 + c * 8) * 2;
        cp16(sbase + sw, srcs[arr] + gb);
    }
}

__global__ __launch_bounds__(128, 3) void fa_kernel(const float* __restrict__ p_param)
{
    extern __shared__ char smem[];
    uint32_t sb = smem_u32(smem);
    const int tid  = threadIdx.x;
    const int w    = tid >> 5;
    const int lane = tid & 31;
    const int quad = lane >> 2;
    const int idq  = lane & 3;
    const int bh = blockIdx.y;
    const int b = bh >> 4, h = bh & 15;
    const int qt = (int)gridDim.x - 1 - (int)blockIdx.x;
    const int q0 = qt * 64;

    {
#pragma unroll
        for (int j = 0; j < 4; j++) {
            int idx = tid + j * 128;
            int row = idx >> 3, c = idx & 7;
            uint32_t sw = row * 128 + ((c ^ (row & 7)) << 4);
            size_t gb = (((size_t)bh * Tn + q0 + row) * 64 + c * 8) * 2;
            cp16(sb + FAQ_H + sw, (const char*)g_Qh + gb);
        }
        fa_load_stage(sb + FASTG0, bh, 0, tid);
        CP_COMMIT();
        if (qt >= 1) fa_load_stage(sb + FASTG0 + FASTG_SZ, bh, 1, tid);
        CP_COMMIT();
    }

    uint32_t Qh[4][4];
    float Of[8][4];
    float m0 = -1e30f, m1 = -1e30f, l0 = 0.0f, l1 = 0.0f;
#pragma unroll
    for (int nf = 0; nf < 8; nf++)
#pragma unroll
        for (int q = 0; q < 4; q++) Of[nf][q] = 0.0f;

    const int k_row = ((lane >> 4) << 3) + (lane & 7);
    const int k_cof = ((lane >> 3) & 1);
    const int v_row = (lane & 15);
    const int v_cof = (lane >> 4);

    for (int kt = 0; kt <= qt; kt++) {
        const uint32_t sbase = sb + FASTG0 + (kt & 1) * FASTG_SZ;
        if (kt < qt) asm volatile("cp.async.wait_group 1;\n" ::: "memory");
        else         asm volatile("cp.async.wait_group 0;\n" ::: "memory");
        __syncthreads();

        if (kt == 0) {
            int row = w * 16 + (lane & 15);
#pragma unroll
            for (int ks = 0; ks < 4; ks++) {
                int c16 = ks * 2 + (lane >> 4);
                uint32_t sw = row * 128 + ((c16 ^ (row & 7)) << 4);
                ldsm4(Qh[ks][0], Qh[ks][1], Qh[ks][2], Qh[ks][3], sb + FAQ_H + sw);
            }
        }

        // ---- S = Qh Kh^T  (fp16, 1 term; log2 domain) ----
        float Sf[8][4];
#pragma unroll
        for (int nf = 0; nf < 8; nf++)
#pragma unroll
            for (int q = 0; q < 4; q++) Sf[nf][q] = 0.0f;

#pragma unroll
        for (int nf2 = 0; nf2 < 4; nf2++) {
            int krow = nf2 * 16 + k_row;
#pragma unroll
            for (int ks = 0; ks < 4; ks++) {
                int c16 = ks * 2 + k_cof;
                uint32_t sw = krow * 128 + ((c16 ^ (krow & 7)) << 4);
                uint32_t kh[4];
                ldsm4(kh[0], kh[1], kh[2], kh[3], sbase + FKH + sw);
                mma16816h(Sf[2*nf2],   Qh[ks], kh);
                mma16816h(Sf[2*nf2+1], Qh[ks], kh + 2);
            }
        }

        if (kt == qt) {
            int r0 = w * 16 + quad, r1 = r0 + 8;
#pragma unroll
            for (int nf = 0; nf < 8; nf++) {
                int c0 = nf * 8 + idq * 2;
                if (c0     > r0) Sf[nf][0] = -1e30f;
                if (c0 + 1 > r0) Sf[nf][1] = -1e30f;
                if (c0     > r1) Sf[nf][2] = -1e30f;
                if (c0 + 1 > r1) Sf[nf][3] = -1e30f;
            }
        }

        // ---- softmax in log2 domain (exp2f) ----
        float mx0 = -1e30f, mx1 = -1e30f;
#pragma unroll
        for (int nf = 0; nf < 8; nf++) {
            mx0 = fmaxf(mx0, fmaxf(Sf[nf][0], Sf[nf][1]));
            mx1 = fmaxf(mx1, fmaxf(Sf[nf][2], Sf[nf][3]));
        }
#pragma unroll
        for (int off = 1; off < 4; off <<= 1) {
            mx0 = fmaxf(mx0, __shfl_xor_sync(0xffffffffu, mx0, off));
            mx1 = fmaxf(mx1, __shfl_xor_sync(0xffffffffu, mx1, off));
        }
        mx0 = fmaxf(mx0, m0);
        mx1 = fmaxf(mx1, m1);
        float a0 = exp2f(m0 - mx0), a1 = exp2f(m1 - mx1);
        m0 = mx0; m1 = mx1;

        float s0 = 0.0f, s1 = 0.0f;
#pragma unroll
        for (int nf = 0; nf < 8; nf++) {
            Sf[nf][0] = exp2f(Sf[nf][0] - mx0);
            Sf[nf][1] = exp2f(Sf[nf][1] - mx0);
            Sf[nf][2] = exp2f(Sf[nf][2] - mx1);
            Sf[nf][3] = exp2f(Sf[nf][3] - mx1);
            s0 += Sf[nf][0] + Sf[nf][1];
            s1 += Sf[nf][2] + Sf[nf][3];
        }
#pragma unroll
        for (int off = 1; off < 4; off <<= 1) {
            s0 += __shfl_xor_sync(0xffffffffu, s0, off);
            s1 += __shfl_xor_sync(0xffffffffu, s1, off);
        }
        l0 = l0 * a0 + s0;
        l1 = l1 * a1 + s1;

#pragma unroll
        for (int nf = 0; nf < 8; nf++) {
            Of[nf][0] *= a0; Of[nf][1] *= a0;
            Of[nf][2] *= a1; Of[nf][3] *= a1;
        }

        // ---- O += P V (P from S frags, bf16x3, ldsm4t V) ----
#pragma unroll
        for (int kf = 0; kf < 4; kf++) {
            uint32_t pha[4], pla[4];
#pragma unroll
            for (int half = 0; half < 2; half++) {
                float* sp = Sf[2*kf + half];
                bfsplit(sp[0], sp[1], pha[half*2+0], pla[half*2+0]);
                bfsplit(sp[2], sp[3], pha[half*2+1], pla[half*2+1]);
            }
            int vrow = kf * 16 + v_row;
#pragma unroll
            for (int nf2 = 0; nf2 < 4; nf2++) {
                int c16 = nf2 * 2 + v_cof;
                uint32_t sw = vrow * 128 + ((c16 ^ (vrow & 7)) << 4);
                uint32_t vh[4], vl[4];
                ldsm4t(vh[0], vh[1], vh[2], vh[3], sbase + FVH + sw);
                ldsm4t(vl[0], vl[1], vl[2], vl[3], sbase + FVL + sw);
                mma16816(Of[2*nf2],   pha, vh);
                mma16816(Of[2*nf2],   pla, vh);
                mma16816(Of[2*nf2],   pha, vl);
                mma16816(Of[2*nf2+1], pha, vh + 2);
                mma16816(Of[2*nf2+1], pla, vh + 2);
                mma16816(Of[2*nf2+1], pha, vl + 2);
            }
        }

        __syncthreads();
        if (kt + 2 <= qt) {
            fa_load_stage(sbase, bh, kt + 2, tid);
            CP_COMMIT();
        }
    }

    // ---- epilogue: p==1: y = mean - 5; else general ----
    const int t0 = q0 + w * 16 + quad;
    const int t1 = t0 + 8;
    float linv0 = 1.0f / l0, linv1 = 1.0f / l1;
#pragma unroll
    for (int nf = 0; nf < 8; nf++) {
        int d0 = nf * 8 + idq * 2;
        int cg = h * 64 + d0;
        float pv0 = clamp_p(p_param[cg]);
        float pv1 = clamp_p(p_param[cg + 1]);
        float me00 = Of[nf][0] * linv0, me01 = Of[nf][1] * linv0;
        float me10 = Of[nf][2] * linv1, me11 = Of[nf][3] * linv1;
        float y00, y01, y10, y11;
        if (pv0 == 1.0f) {
            y00 = me00 - 5.0f;
            y10 = me10 - 5.0f;
        } else {
            float zm0 = g_zmax[b*Cn + cg];
            y00 = __expf((zm0 + __logf(me00)) / pv0) - 5.0f;
            y10 = __expf((zm0 + __logf(me10)) / pv0) - 5.0f;
        }
        if (pv1 == 1.0f) {
            y01 = me01 - 5.0f;
            y11 = me11 - 5.0f;
        } else {
            float zm1 = g_zmax[b*Cn + cg + 1];
            y01 = __expf((zm1 + __logf(me01)) / pv1) - 5.0f;
            y11 = __expf((zm1 + __logf(me11)) / pv1) - 5.0f;
        }
        size_t i0 = ((size_t)(b*Tn + t0)*Cn + cg) >> 1;
        size_t i1 = ((size_t)(b*Tn + t1)*Cn + cg) >> 1;
        ((uint32_t*)gA_hi)[i0] = pkhf(y00, y01);
        ((uint32_t*)gA_hi)[i1] = pkhf(y10, y11);
    }
}

// ---------------------------------------------------------------------------

extern "C" void kernel_launch(void* const* d_in, const int* in_sizes, int n_in,
                              void* d_out, int out_size)
{
    const float* x       = (const float*)d_in[0];
    const float* w_attn  = (const float*)d_in[1];
    const float* b_attn  = (const float*)d_in[2];
    const float* w_proj  = (const float*)d_in[3];
    const float* b_proj  = (const float*)d_in[4];
    const float* p_param = (const float*)d_in[5];
    float* out = (float*)d_out;

    void *ah, *bth, *bt2;
    cudaGetSymbolAddress(&ah,  gA_hi);
    cudaGetSymbolAddress(&bth, gBT_hi);
    cudaGetSymbolAddress(&bt2, gBT2);

    cudaFuncSetAttribute(fa_kernel, cudaFuncAttributeMaxDynamicSharedMemorySize, FA_SMEM);
    cudaFuncSetAttribute(tc_gemm<0>, cudaFuncAttributeMaxDynamicSharedMemorySize, TCG_SMEM);
    cudaFuncSetAttribute(tc_gemm<1>, cudaFuncAttributeMaxDynamicSharedMemorySize, TCG_SMEM);

    // 1) mega prep: conv x -> fp16, transpose w_attn, transpose w_proj
    prep_kernel<<<8192, 256>>>(x, w_attn, w_proj);

    // 2) QKV GEMM + scatter; V transform fused for p==1 channels
    tc_gemm<1><<<dim3(3072/128, Mn/128), 256, TCG_SMEM>>>(
        (const __half*)ah, (const __half*)bth, b_attn, nullptr, p_param);

    // 3) w-range partials (p!=1 only) + fused reduce/V-fixup
    zmax_part<<<dim3(BHn, 16), 256>>>(p_param);
    vexp_kernel<<<(BHn*Tn*Dn)/1024, 256>>>(p_param);

    // 4) tensor-core causal FA (3 CTAs/SM, log2-domain softmax)
    fa_kernel<<<dim3(Tn/64, BHn), 128, FA_SMEM>>>(p_param);

    // 5) proj GEMM (fp16 single-term)
    tc_gemm<0><<<dim3(Cn/128, Mn/128), 256, TCG_SMEM>>>(
        (const __half*)ah, (const __half*)bt2, b_proj, out, nullptr);
}

// round 16
// speedup vs baseline: 1.0346x; 1.0346x over previous
#include <cuda_runtime.h>
#include <cuda_bf16.h>
#include <cuda_fp16.h>
#include <math.h>
#include <stdint.h>

#define Bn 2
#define Tn 2048
#define Cn 1024
#define Hn 16
#define Dn 64
#define Mn (Bn*Tn)          // 4096
#define BHn (Bn*Hn)         // 32

typedef unsigned long long ull;

// ---------------- device scratch ----------------
__device__ __half         g_Qh[BHn*Tn*Dn];  // head-major, pre-scaled by 0.125*log2e
__device__ __half         g_Kh[BHn*Tn*Dn];  // fp16 hi only
__device__ float          g_V [BHn*Tn*Dn];  // raw v (fp32) -- only for p!=1 channels
__device__ __nv_bfloat16  g_Vh[BHn*Tn*Dn];  // transformed V bf16 hi/lo
__device__ __nv_bfloat16  g_Vl[BHn*Tn*Dn];
__device__ float g_zmax[Bn*Cn];
__device__ float g_zpmax[16*Bn*Cn];         // partial wmax (p!=1 only)
__device__ float g_zpmin[16*Bn*Cn];         // partial wmin (p!=1 only)
__device__ __half gA_hi[Mn*Cn];             // fp16 A operand (x conv, then Y from FA)
__device__ __half gBT_hi[3*Cn*Cn];          // fp16 w_attn^T
__device__ __half gBT2  [Cn*Cn];            // fp16 w_proj^T

#define QSCALE 0.18033688f   // 0.125 * log2(e)

__device__ __forceinline__ float clamp_p(float pp) {
    float sgn = (pp >= 0.0f) ? 1.0f : -1.0f;
    return sgn * fminf(fmaxf(fabsf(pp), 1e-4f), 1e3f);
}

// ---------------- ptx helpers ----------------
__device__ __forceinline__ uint32_t smem_u32(const void* p) {
    uint32_t a;
    asm("{ .reg .u64 t; cvta.to.shared.u64 t, %1; cvt.u32.u64 %0, t; }" : "=r"(a) : "l"(p));
    return a;
}
__device__ __forceinline__ float ex2(float x) {
    float r;
    asm("ex2.approx.f32 %0, %1;" : "=f"(r) : "f"(x));
    return r;
}
__device__ __forceinline__ void cp16(uint32_t dst, const void* src) {
    asm volatile("cp.async.cg.shared.global [%0], [%1], 16;\n" :: "r"(dst), "l"(src));
}
#define CP_COMMIT() asm volatile("cp.async.commit_group;\n" ::: "memory")

__device__ __forceinline__ void ldsm4(uint32_t& r0, uint32_t& r1, uint32_t& r2, uint32_t& r3,
                                      uint32_t addr) {
    asm volatile("ldmatrix.sync.aligned.m8n8.x4.shared.b16 {%0,%1,%2,%3}, [%4];"
                 : "=r"(r0), "=r"(r1), "=r"(r2), "=r"(r3) : "r"(addr));
}
__device__ __forceinline__ void ldsm4t(uint32_t& r0, uint32_t& r1, uint32_t& r2, uint32_t& r3,
                                       uint32_t addr) {
    asm volatile("ldmatrix.sync.aligned.m8n8.x4.trans.shared.b16 {%0,%1,%2,%3}, [%4];"
                 : "=r"(r0), "=r"(r1), "=r"(r2), "=r"(r3) : "r"(addr));
}
__device__ __forceinline__ void mma16816(float* c, const uint32_t* a, const uint32_t* b) {
    asm volatile(
        "mma.sync.aligned.m16n8k16.row.col.f32.bf16.bf16.f32 "
        "{%0,%1,%2,%3}, {%4,%5,%6,%7}, {%8,%9}, {%0,%1,%2,%3};"
        : "+f"(c[0]), "+f"(c[1]), "+f"(c[2]), "+f"(c[3])
        : "r"(a[0]), "r"(a[1]), "r"(a[2]), "r"(a[3]), "r"(b[0]), "r"(b[1]));
}
__device__ __forceinline__ void mma16816h(float* c, const uint32_t* a, const uint32_t* b) {
    asm volatile(
        "mma.sync.aligned.m16n8k16.row.col.f32.f16.f16.f32 "
        "{%0,%1,%2,%3}, {%4,%5,%6,%7}, {%8,%9}, {%0,%1,%2,%3};"
        : "+f"(c[0]), "+f"(c[1]), "+f"(c[2]), "+f"(c[3])
        : "r"(a[0]), "r"(a[1]), "r"(a[2]), "r"(a[3]), "r"(b[0]), "r"(b[1]));
}
__device__ __forceinline__ uint32_t pkbf(float lo, float hi) {
    uint32_t r;
    asm("cvt.rn.bf16x2.f32 %0, %1, %2;" : "=r"(r) : "f"(hi), "f"(lo));
    return r;
}
__device__ __forceinline__ uint32_t pkhf(float lo, float hi) {
    uint32_t r;
    asm("cvt.rn.f16x2.f32 %0, %1, %2;" : "=r"(r) : "f"(hi), "f"(lo));
    return r;
}
__device__ __forceinline__ void bfsplit(float a, float b, uint32_t& hi, uint32_t& lo) {
    hi = pkbf(a, b);
    float f0 = __uint_as_float(hi << 16);
    float f1 = __uint_as_float(hi & 0xffff0000u);
    lo = pkbf(a - f0, b - f1);
}

// ---------------------------------------------------------------------------
// mega prep: [0,4096) conv x->fp16; [4096,7168) transpose w_attn;
// [7168,8192) transpose w_proj.
// ---------------------------------------------------------------------------
__global__ __launch_bounds__(256) void prep_kernel(
    const float* __restrict__ x,
    const float* __restrict__ w_attn,
    const float* __restrict__ w_proj)
{
    __shared__ float tile[32][33];
    int bid = blockIdx.x;
    int tid = threadIdx.x;
    if (bid < 4096) {
        int i = bid * 256 + tid;
        float4 a = ((const float4*)x)[i];
        ((uint2*)gA_hi)[i] = make_uint2(pkhf(a.x, a.y), pkhf(a.z, a.w));
        return;
    }
    const float* W;
    __half* Th;
    int Nd, bx, by;
    if (bid < 7168) {
        int t = bid - 4096;
        W = w_attn; Th = gBT_hi; Nd = 3072;
        bx = t % 96; by = t / 96;
    } else {
        int t = bid - 7168;
        W = w_proj; Th = gBT2; Nd = 1024;
        bx = t % 32; by = t / 32;
    }
    int nx = bx * 32, kx = by * 32;
    int tx = tid & 31, ty = tid >> 5;
#pragma unroll
    for (int r = ty; r < 32; r += 8)
        tile[r][tx] = W[(size_t)(kx + r) * Nd + nx + tx];
    __syncthreads();
#pragma unroll
    for (int r = ty; r < 32; r += 8) {
        size_t o = (size_t)(nx + r) * 1024 + kx + tx;
        Th[o] = __float2half_rn(tile[tx][r]);
    }
}

// ---------------------------------------------------------------------------
// fp16 single-term mma.sync GEMM: CTA 128x128, warp tile 64x32 (2x4 warps),
// BK=64, cp.async double buffer, 64 KB smem.
// ---------------------------------------------------------------------------
#define G_BHI 16384
#define G_STG 32768
#define TCG_SMEM (2*G_STG)   // 64 KB

__device__ __forceinline__ void load_stage(
    uint32_t sbase,
    const __half* __restrict__ Ah, const __half* __restrict__ Bh,
    int m0, int n0, int k0, int tid)
{
#pragma unroll
    for (int j = 0; j < 4; j++) {
        int idx = tid + j * 256;
        int row = idx >> 3, c = idx & 7;
        uint32_t sw = row * 128 + ((c ^ (row & 7)) << 4);
        size_t ga = (size_t)(m0 + row) * 1024 + k0 + c * 8;
        cp16(sbase + sw, Ah + ga);
    }
#pragma unroll
    for (int j = 0; j < 4; j++) {
        int idx = tid + j * 256;
        int row = idx >> 3, c = idx & 7;
        uint32_t sw = row * 128 + ((c ^ (row & 7)) << 4);
        size_t gb = (size_t)(n0 + row) * 1024 + k0 + c * 8;
        cp16(sbase + G_BHI + sw, Bh + gb);
    }
}

template<int MODE>
__global__ __launch_bounds__(256, 2) void tc_gemm(
    const __half* __restrict__ Ah, const __half* __restrict__ Bh,
    const float* __restrict__ bias, float* __restrict__ Cout,
    const float* __restrict__ p_param)
{
    extern __shared__ char smem[];
    uint32_t sb = smem_u32(smem);
    const int tid  = threadIdx.x;
    const int wid  = tid >> 5;
    const int lane = tid & 31;
    const int wm = wid & 1;
    const int wn = wid >> 1;
    const int m0 = blockIdx.y * 128;
    const int n0 = blockIdx.x * 128;

    float acc[4][4][4];
#pragma unroll
    for (int i = 0; i < 4; i++)
#pragma unroll
        for (int j = 0; j < 4; j++)
#pragma unroll
            for (int q = 0; q < 4; q++) acc[i][j][q] = 0.0f;

    load_stage(sb,         Ah, Bh, m0, n0, 0,  tid); CP_COMMIT();
    load_stage(sb + G_STG, Ah, Bh, m0, n0, 64, tid); CP_COMMIT();

    const int a_row = wm * 64 + (lane & 15);
    const int a_c16 = (lane >> 4);
    const int b_row = wn * 32 + ((lane >> 4) << 3) + (lane & 7);
    const int b_cof = ((lane >> 3) & 1);

    for (int it = 0; it < 16; it++) {
        const int s = it & 1;
        const uint32_t sbase = sb + s * G_STG;
        if (it < 15) asm volatile("cp.async.wait_group 1;\n" ::: "memory");
        else         asm volatile("cp.async.wait_group 0;\n" ::: "memory");
        __syncthreads();

#pragma unroll
        for (int ks = 0; ks < 4; ks++) {
            uint32_t ahi[4][4];
#pragma unroll
            for (int mf = 0; mf < 4; mf++) {
                int row = a_row + mf * 16;
                int c16 = ks * 2 + a_c16;
                uint32_t ad = sbase + row * 128 + ((c16 ^ (row & 7)) << 4);
                ldsm4(ahi[mf][0], ahi[mf][1], ahi[mf][2], ahi[mf][3], ad);
            }
#pragma unroll
            for (int nf2 = 0; nf2 < 2; nf2++) {
                int row = b_row + nf2 * 16;
                int c16 = ks * 2 + b_cof;
                uint32_t bd = sbase + G_BHI + row * 128 + ((c16 ^ (row & 7)) << 4);
                uint32_t bh4[4];
                ldsm4(bh4[0], bh4[1], bh4[2], bh4[3], bd);
#pragma unroll
                for (int mf = 0; mf < 4; mf++) {
                    mma16816h(acc[mf][2*nf2],   ahi[mf], bh4);
                    mma16816h(acc[mf][2*nf2+1], ahi[mf], bh4 + 2);
                }
            }
        }
        __syncthreads();
        if (it + 2 < 16) {
            load_stage(sbase, Ah, Bh, m0, n0, (it + 2) * 64, tid);
            CP_COMMIT();
        }
    }

    const int mbase = m0 + wm * 64 + (lane >> 2);
    const int nbase = n0 + wn * 32 + (lane & 3) * 2;
    const int sec = n0 >> 10;
    float pp0[4], pp1[4];
    if (MODE == 1 && sec == 2) {
#pragma unroll
        for (int nf = 0; nf < 4; nf++) {
            int c1 = (nbase + nf * 8) & 1023;
            pp0[nf] = clamp_p(p_param[c1]);
            pp1[nf] = clamp_p(p_param[c1 + 1]);
        }
    }
#pragma unroll
    for (int mf = 0; mf < 4; mf++) {
#pragma unroll
        for (int half = 0; half < 2; half++) {
            int m = mbase + mf * 16 + half * 8;
#pragma unroll
            for (int nf = 0; nf < 4; nf++) {
                int n = nbase + nf * 8;
                float v0 = acc[mf][nf][half*2+0] + bias[n];
                float v1 = acc[mf][nf][half*2+1] + bias[n+1];
                if (MODE == 0) {
                    *(float2*)(Cout + (size_t)m * Cn + n) = make_float2(v0, v1);
                } else {
                    int c1  = n & 1023;
                    int h   = c1 >> 6, dd = c1 & 63;
                    int bq  = m >> 11, t = m & 2047;
                    size_t idx = ((size_t)((bq * Hn + h) * Tn + t)) * 64 + dd;
                    if (sec == 2) {
                        if (pp0[nf] == 1.0f && pp1[nf] == 1.0f) {
                            float w0 = fmaxf(fabsf(v0 + 5.0f), 1e-10f);
                            float w1 = fmaxf(fabsf(v1 + 5.0f), 1e-10f);
                            uint32_t hh, ll;
                            bfsplit(w0, w1, hh, ll);
                            ((uint32_t*)g_Vh)[idx >> 1] = hh;
                            ((uint32_t*)g_Vl)[idx >> 1] = ll;
                        } else {
                            *(float2*)(g_V + idx) = make_float2(v0, v1);
                        }
                    } else if (sec == 1) {
                        *(uint32_t*)(g_Kh + idx) = pkhf(v0, v1);
                    } else {
                        *(uint32_t*)(g_Qh + idx) = pkhf(v0 * QSCALE, v1 * QSCALE);
                    }
                }
            }
        }
    }
}

// ---------------------------------------------------------------------------
// w-range partial: only for channels with p != 1
// ---------------------------------------------------------------------------
__global__ __launch_bounds__(256) void zmax_part(const float* __restrict__ p_param)
{
    int bh = blockIdx.x, chunk = blockIdx.y;
    int b = bh >> 4, h = bh & 15;
    int d4 = threadIdx.x & 15;
    int g  = threadIdx.x >> 4;
    int c  = h*64 + d4*4;

    bool need = (clamp_p(p_param[c+0]) != 1.0f) || (clamp_p(p_param[c+1]) != 1.0f) ||
                (clamp_p(p_param[c+2]) != 1.0f) || (clamp_p(p_param[c+3]) != 1.0f);

    float4 mx = make_float4(-1e30f, -1e30f, -1e30f, -1e30f);
    float4 mn = make_float4( 1e30f,  1e30f,  1e30f,  1e30f);
    if (need) {
        const float* vp = g_V + (size_t)bh * Tn * 64;
        for (int t = chunk*128 + g; t < (chunk+1)*128; t += 16) {
            float4 v = *(const float4*)(vp + t*64 + d4*4);
            float w0 = fmaxf(fabsf(v.x + 5.0f), 1e-10f);
            float w1 = fmaxf(fabsf(v.y + 5.0f), 1e-10f);
            float w2 = fmaxf(fabsf(v.z + 5.0f), 1e-10f);
            float w3 = fmaxf(fabsf(v.w + 5.0f), 1e-10f);
            mx.x = fmaxf(mx.x, w0); mn.x = fminf(mn.x, w0);
            mx.y = fmaxf(mx.y, w1); mn.y = fminf(mn.y, w1);
            mx.z = fmaxf(mx.z, w2); mn.z = fminf(mn.z, w2);
            mx.w = fmaxf(mx.w, w3); mn.w = fminf(mn.w, w3);
        }
    }
    __shared__ float4 redx[256];
    __shared__ float4 redn[256];
    redx[threadIdx.x] = mx;
    redn[threadIdx.x] = mn;
    __syncthreads();
    if (threadIdx.x < 16) {
        float4 m = redx[threadIdx.x];
        float4 q = redn[threadIdx.x];
#pragma unroll
        for (int gg = 1; gg < 16; gg++) {
            float4 o = redx[gg*16 + threadIdx.x];
            float4 u = redn[gg*16 + threadIdx.x];
            m.x = fmaxf(m.x, o.x); m.y = fmaxf(m.y, o.y);
            m.z = fmaxf(m.z, o.z); m.w = fmaxf(m.w, o.w);
            q.x = fminf(q.x, u.x); q.y = fminf(q.y, u.y);
            q.z = fminf(q.z, u.z); q.w = fminf(q.w, u.w);
        }
        int off = chunk*(Bn*Cn) + b*Cn + h*64 + threadIdx.x*4;
        *(float4*)(g_zpmax + off) = m;
        *(float4*)(g_zpmin + off) = q;
    }
}

// ---------------------------------------------------------------------------
// V transform fixup + inline zmax reduce: only for p != 1 channels.
// Block 0..7 additionally publish g_zmax for the FA epilogue.
// ---------------------------------------------------------------------------
__device__ __forceinline__ float reduce_zmax(int i, float p) {
    float wmax = -1e30f, wmin = 1e30f;
#pragma unroll
    for (int ch = 0; ch < 16; ch++) {
        wmax = fmaxf(wmax, g_zpmax[ch*(Bn*Cn) + i]);
        wmin = fminf(wmin, g_zpmin[ch*(Bn*Cn) + i]);
    }
    return (p >= 0.0f) ? p * __logf(wmax) : p * __logf(wmin);
}

__global__ __launch_bounds__(256) void vexp_kernel(const float* __restrict__ p_param)
{
    int i = blockIdx.x * 256 + threadIdx.x;
    int base = i * 4;
    int dd = base & 63;
    int bh = base >> 17;
    int h = bh & 15, b = bh >> 4;
    int c = h*64 + dd;
    float p0 = clamp_p(p_param[c+0]), p1 = clamp_p(p_param[c+1]);
    float p2 = clamp_p(p_param[c+2]), p3 = clamp_p(p_param[c+3]);
    bool f01 = (p0 == 1.0f) && (p1 == 1.0f);
    bool f23 = (p2 == 1.0f) && (p3 == 1.0f);
    if (blockIdx.x < 8) {
        int gi = blockIdx.x * 256 + threadIdx.x;
        float pg = clamp_p(p_param[gi & (Cn-1)]);
        g_zmax[gi] = (pg == 1.0f) ? 0.0f : reduce_zmax(gi, pg);
    }
    if (f01 && f23) return;
    if (!f01) {
        float zm0 = (p0 == 1.0f) ? 0.0f : reduce_zmax(b*Cn + c,     p0);
        float zm1 = (p1 == 1.0f) ? 0.0f : reduce_zmax(b*Cn + c + 1, p1);
        float2 v = *(const float2*)(g_V + base);
        float w0 = fmaxf(fabsf(v.x + 5.0f), 1e-10f);
        float w1 = fmaxf(fabsf(v.y + 5.0f), 1e-10f);
        float e0 = (p0 == 1.0f) ? w0 : __expf(p0 * __logf(w0) - zm0);
        float e1 = (p1 == 1.0f) ? w1 : __expf(p1 * __logf(w1) - zm1);
        uint32_t hh, ll;
        bfsplit(e0, e1, hh, ll);
        ((uint32_t*)g_Vh)[base >> 1] = hh;
        ((uint32_t*)g_Vl)[base >> 1] = ll;
    }
    if (!f23) {
        float zm2 = (p2 == 1.0f) ? 0.0f : reduce_zmax(b*Cn + c + 2, p2);
        float zm3 = (p3 == 1.0f) ? 0.0f : reduce_zmax(b*Cn + c + 3, p3);
        float2 v = *(const float2*)(g_V + base + 2);
        float w0 = fmaxf(fabsf(v.x + 5.0f), 1e-10f);
        float w1 = fmaxf(fabsf(v.y + 5.0f), 1e-10f);
        float e0 = (p2 == 1.0f) ? w0 : __expf(p2 * __logf(w0) - zm2);
        float e1 = (p3 == 1.0f) ? w1 : __expf(p3 * __logf(w1) - zm3);
        uint32_t hh, ll;
        bfsplit(e0, e1, hh, ll);
        ((uint32_t*)g_Vh)[(base + 2) >> 1] = hh;
        ((uint32_t*)g_Vl)[(base + 2) >> 1] = ll;
    }
}

// ---------------------------------------------------------------------------
// Tensor-core flash attention (causal), BQ=BK=64, 4 warps, 56 KB smem,
// 2 CTAs/SM. S in log2 domain (Q pre-scaled by 0.125*log2e), ex2.approx
// softmax. S = fp16 1-term Qh·Kh; P·V bf16 3-term. p==1: y = mean - 5.
// ---------------------------------------------------------------------------
#define FAQ_H 0
#define FASTG0 8192
#define FASTG_SZ 24576
#define FKH 0
#define FVH 8192
#define FVL 16384
#define FA_SMEM (8192 + 2*FASTG_SZ)   // 56 KB

__device__ __forceinline__ void fa_load_stage(uint32_t sbase, int bh, int kt, int tid)
{
    const char* srcs[3] = {(const char*)g_Kh, (const char*)g_Vh, (const char*)g_Vl};
#pragma unroll
    for (int j = 0; j < 12; j++) {
        int idx = tid + j * 128;
        int arr = idx >> 9;
        int rem = idx & 511;
        int row = rem >> 3, c = rem & 7;
        uint32_t sw = arr * 8192 + row * 128 + ((c ^ (row & 7)) << 4);
        size_t gb = (((size_t)bh * Tn + kt * 64 + row) * 64 + c * 8) * 2;
        cp16(sbase + sw, srcs[arr] + gb);
    }
}

__global__ __launch_bounds__(128) void fa_kernel(const float* __restrict__ p_param)
{
    extern __shared__ char smem[];
    uint32_t sb = smem_u32(smem);
    const int tid  = threadIdx.x;
    const int w    = tid >> 5;
    const int lane = tid & 31;
    const int quad = lane >> 2;
    const int idq  = lane & 3;
    const int bh = blockIdx.y;
    const int b = bh >> 4, h = bh & 15;
    const int qt = (int)gridDim.x - 1 - (int)blockIdx.x;
    const int q0 = qt * 64;

    {
#pragma unroll
        for (int j = 0; j < 4; j++) {
            int idx = tid + j * 128;
            int row = idx >> 3, c = idx & 7;
            uint32_t sw = row * 128 + ((c ^ (row & 7)) << 4);
            size_t gb = (((size_t)bh * Tn + q0 + row) * 64 + c * 8) * 2;
            cp16(sb + FAQ_H + sw, (const char*)g_Qh + gb);
        }
        fa_load_stage(sb + FASTG0, bh, 0, tid);
        CP_COMMIT();
        if (qt >= 1) fa_load_stage(sb + FASTG0 + FASTG_SZ, bh, 1, tid);
        CP_COMMIT();
    }

    uint32_t Qh[4][4];
    float Of[8][4];
    float m0 = -1e30f, m1 = -1e30f, l0 = 0.0f, l1 = 0.0f;
#pragma unroll
    for (int nf = 0; nf < 8; nf++)
#pragma unroll
        for (int q = 0; q < 4; q++) Of[nf][q] = 0.0f;

    const int k_row = ((lane >> 4) << 3) + (lane & 7);
    const int k_cof = ((lane >> 3) & 1);
    const int v_row = (lane & 15);
    const int v_cof = (lane >> 4);

    for (int kt = 0; kt <= qt; kt++) {
        const uint32_t sbase = sb + FASTG0 + (kt & 1) * FASTG_SZ;
        if (kt < qt) asm volatile("cp.async.wait_group 1;\n" ::: "memory");
        else         asm volatile("cp.async.wait_group 0;\n" ::: "memory");
        __syncthreads();

        if (kt == 0) {
            int row = w * 16 + (lane & 15);
#pragma unroll
            for (int ks = 0; ks < 4; ks++) {
                int c16 = ks * 2 + (lane >> 4);
                uint32_t sw = row * 128 + ((c16 ^ (row & 7)) << 4);
                ldsm4(Qh[ks][0], Qh[ks][1], Qh[ks][2], Qh[ks][3], sb + FAQ_H + sw);
            }
        }

        // ---- S = Qh Kh^T  (fp16, 1 term; log2 domain) ----
        float Sf[8][4];
#pragma unroll
        for (int nf = 0; nf < 8; nf++)
#pragma unroll
            for (int q = 0; q < 4; q++) Sf[nf][q] = 0.0f;

#pragma unroll
        for (int nf2 = 0; nf2 < 4; nf2++) {
            int krow = nf2 * 16 + k_row;
#pragma unroll
            for (int ks = 0; ks < 4; ks++) {
                int c16 = ks * 2 + k_cof;
                uint32_t sw = krow * 128 + ((c16 ^ (krow & 7)) << 4);
                uint32_t kh[4];
                ldsm4(kh[0], kh[1], kh[2], kh[3], sbase + FKH + sw);
                mma16816h(Sf[2*nf2],   Qh[ks], kh);
                mma16816h(Sf[2*nf2+1], Qh[ks], kh + 2);
            }
        }

        if (kt == qt) {
            int r0 = w * 16 + quad, r1 = r0 + 8;
#pragma unroll
            for (int nf = 0; nf < 8; nf++) {
                int c0 = nf * 8 + idq * 2;
                if (c0     > r0) Sf[nf][0] = -1e30f;
                if (c0 + 1 > r0) Sf[nf][1] = -1e30f;
                if (c0     > r1) Sf[nf][2] = -1e30f;
                if (c0 + 1 > r1) Sf[nf][3] = -1e30f;
            }
        }

        // ---- softmax in log2 domain (raw ex2.approx MUFU) ----
        float mx0 = -1e30f, mx1 = -1e30f;
#pragma unroll
        for (int nf = 0; nf < 8; nf++) {
            mx0 = fmaxf(mx0, fmaxf(Sf[nf][0], Sf[nf][1]));
            mx1 = fmaxf(mx1, fmaxf(Sf[nf][2], Sf[nf][3]));
        }
#pragma unroll
        for (int off = 1; off < 4; off <<= 1) {
            mx0 = fmaxf(mx0, __shfl_xor_sync(0xffffffffu, mx0, off));
            mx1 = fmaxf(mx1, __shfl_xor_sync(0xffffffffu, mx1, off));
        }
        mx0 = fmaxf(mx0, m0);
        mx1 = fmaxf(mx1, m1);
        float a0 = ex2(m0 - mx0), a1 = ex2(m1 - mx1);
        m0 = mx0; m1 = mx1;

        float s0 = 0.0f, s1 = 0.0f;
#pragma unroll
        for (int nf = 0; nf < 8; nf++) {
            Sf[nf][0] = ex2(Sf[nf][0] - mx0);
            Sf[nf][1] = ex2(Sf[nf][1] - mx0);
            Sf[nf][2] = ex2(Sf[nf][2] - mx1);
            Sf[nf][3] = ex2(Sf[nf][3] - mx1);
            s0 += Sf[nf][0] + Sf[nf][1];
            s1 += Sf[nf][2] + Sf[nf][3];
        }
#pragma unroll
        for (int off = 1; off < 4; off <<= 1) {
            s0 += __shfl_xor_sync(0xffffffffu, s0, off);
            s1 += __shfl_xor_sync(0xffffffffu, s1, off);
        }
        l0 = l0 * a0 + s0;
        l1 = l1 * a1 + s1;

#pragma unroll
        for (int nf = 0; nf < 8; nf++) {
            Of[nf][0] *= a0; Of[nf][1] *= a0;
            Of[nf][2] *= a1; Of[nf][3] *= a1;
        }

        // ---- O += P V (P from S frags, bf16x3, ldsm4t V) ----
#pragma unroll
        for (int kf = 0; kf < 4; kf++) {
            uint32_t pha[4], pla[4];
#pragma unroll
            for (int half = 0; half < 2; half++) {
                float* sp = Sf[2*kf + half];
                bfsplit(sp[0], sp[1], pha[half*2+0], pla[half*2+0]);
                bfsplit(sp[2], sp[3], pha[half*2+1], pla[half*2+1]);
            }
            int vrow = kf * 16 + v_row;
#pragma unroll
            for (int nf2 = 0; nf2 < 4; nf2++) {
                int c16 = nf2 * 2 + v_cof;
                uint32_t sw = vrow * 128 + ((c16 ^ (vrow & 7)) << 4);
                uint32_t vh[4], vl[4];
                ldsm4t(vh[0], vh[1], vh[2], vh[3], sbase + FVH + sw);
                ldsm4t(vl[0], vl[1], vl[2], vl[3], sbase + FVL + sw);
                mma16816(Of[2*nf2],   pha, vh);
                mma16816(Of[2*nf2],   pla, vh);
                mma16816(Of[2*nf2],   pha, vl);
                mma16816(Of[2*nf2+1], pha, vh + 2);
                mma16816(Of[2*nf2+1], pla, vh + 2);
                mma16816(Of[2*nf2+1], pha, vl + 2);
            }
        }

        __syncthreads();
        if (kt + 2 <= qt) {
            fa_load_stage(sbase, bh, kt + 2, tid);
            CP_COMMIT();
        }
    }

    // ---- epilogue: p==1: y = mean - 5; else general ----
    const int t0 = q0 + w * 16 + quad;
    const int t1 = t0 + 8;
    float linv0 = 1.0f / l0, linv1 = 1.0f / l1;
#pragma unroll
    for (int nf = 0; nf < 8; nf++) {
        int d0 = nf * 8 + idq * 2;
        int cg = h * 64 + d0;
        float pv0 = clamp_p(p_param[cg]);
        float pv1 = clamp_p(p_param[cg + 1]);
        float me00 = Of[nf][0] * linv0, me01 = Of[nf][1] * linv0;
        float me10 = Of[nf][2] * linv1, me11 = Of[nf][3] * linv1;
        float y00, y01, y10, y11;
        if (pv0 == 1.0f) {
            y00 = me00 - 5.0f;
            y10 = me10 - 5.0f;
        } else {
            float zm0 = g_zmax[b*Cn + cg];
            y00 = __expf((zm0 + __logf(me00)) / pv0) - 5.0f;
            y10 = __expf((zm0 + __logf(me10)) / pv0) - 5.0f;
        }
        if (pv1 == 1.0f) {
            y01 = me01 - 5.0f;
            y11 = me11 - 5.0f;
        } else {
            float zm1 = g_zmax[b*Cn + cg + 1];
            y01 = __expf((zm1 + __logf(me01)) / pv1) - 5.0f;
            y11 = __expf((zm1 + __logf(me11)) / pv1) - 5.0f;
        }
        size_t i0 = ((size_t)(b*Tn + t0)*Cn + cg) >> 1;
        size_t i1 = ((size_t)(b*Tn + t1)*Cn + cg) >> 1;
        ((uint32_t*)gA_hi)[i0] = pkhf(y00, y01);
        ((uint32_t*)gA_hi)[i1] = pkhf(y10, y11);
    }
}

// ---------------------------------------------------------------------------

extern "C" void kernel_launch(void* const* d_in, const int* in_sizes, int n_in,
                              void* d_out, int out_size)
{
    const float* x       = (const float*)d_in[0];
    const float* w_attn  = (const float*)d_in[1];
    const float* b_attn  = (const float*)d_in[2];
    const float* w_proj  = (const float*)d_in[3];
    const float* b_proj  = (const float*)d_in[4];
    const float* p_param = (const float*)d_in[5];
    float* out = (float*)d_out;

    void *ah, *bth, *bt2;
    cudaGetSymbolAddress(&ah,  gA_hi);
    cudaGetSymbolAddress(&bth, gBT_hi);
    cudaGetSymbolAddress(&bt2, gBT2);

    cudaFuncSetAttribute(fa_kernel, cudaFuncAttributeMaxDynamicSharedMemorySize, FA_SMEM);
    cudaFuncSetAttribute(tc_gemm<0>, cudaFuncAttributeMaxDynamicSharedMemorySize, TCG_SMEM);
    cudaFuncSetAttribute(tc_gemm<1>, cudaFuncAttributeMaxDynamicSharedMemorySize, TCG_SMEM);

    // 1) mega prep: conv x -> fp16, transpose w_attn, transpose w_proj
    prep_kernel<<<8192, 256>>>(x, w_attn, w_proj);

    // 2) QKV GEMM + scatter; V transform fused for p==1 channels
    tc_gemm<1><<<dim3(3072/128, Mn/128), 256, TCG_SMEM>>>(
        (const __half*)ah, (const __half*)bth, b_attn, nullptr, p_param);

    // 3) w-range partials (p!=1 only) + fused reduce/V-fixup
    zmax_part<<<dim3(BHn, 16), 256>>>(p_param);
    vexp_kernel<<<(BHn*Tn*Dn)/1024, 256>>>(p_param);

    // 4) tensor-core causal FA (2 CTAs/SM, ex2.approx log2-domain softmax)
    fa_kernel<<<dim3(Tn/64, BHn), 128, FA_SMEM>>>(p_param);

    // 5) proj GEMM (fp16 single-term)
    tc_gemm<0><<<dim3(Cn/128, Mn/128), 256, TCG_SMEM>>>(
        (const __half*)ah, (const __half*)bt2, b_proj, out, nullptr);
}

// round 17
// speedup vs baseline: 1.0359x; 1.0012x over previous
#include <cuda_runtime.h>
#include <cuda_bf16.h>
#include <cuda_fp16.h>
#include <math.h>
#include <stdint.h>

#define Bn 2
#define Tn 2048
#define Cn 1024
#define Hn 16
#define Dn 64
#define Mn (Bn*Tn)          // 4096
#define BHn (Bn*Hn)         // 32

typedef unsigned long long ull;

// ---------------- device scratch ----------------
__device__ __half         g_Qh[BHn*Tn*Dn];  // head-major, pre-scaled by 0.125*log2e
__device__ __half         g_Kh[BHn*Tn*Dn];  // fp16 hi only
__device__ float          g_V [BHn*Tn*Dn];  // raw v (fp32) -- only for p!=1 channels
__device__ __nv_bfloat16  g_Vh[BHn*Tn*Dn];  // transformed V bf16 hi/lo
__device__ __nv_bfloat16  g_Vl[BHn*Tn*Dn];
__device__ float g_zmax[Bn*Cn];
__device__ float g_zpmax[16*Bn*Cn];         // partial wmax (p!=1 only)
__device__ float g_zpmin[16*Bn*Cn];         // partial wmin (p!=1 only)
__device__ __half gA_hi[Mn*Cn];             // fp16 A operand (x conv, then Y from FA)
__device__ __half gBT_hi[3*Cn*Cn];          // fp16 w_attn^T
__device__ __half gBT2  [Cn*Cn];            // fp16 w_proj^T

#define QSCALE 0.18033688f   // 0.125 * log2(e)

__device__ __forceinline__ float clamp_p(float pp) {
    float sgn = (pp >= 0.0f) ? 1.0f : -1.0f;
    return sgn * fminf(fmaxf(fabsf(pp), 1e-4f), 1e3f);
}

// ---------------- ptx helpers ----------------
__device__ __forceinline__ uint32_t smem_u32(const void* p) {
    uint32_t a;
    asm("{ .reg .u64 t; cvta.to.shared.u64 t, %1; cvt.u32.u64 %0, t; }" : "=r"(a) : "l"(p));
    return a;
}
__device__ __forceinline__ float ex2(float x) {
    float r;
    asm("ex2.approx.f32 %0, %1;" : "=f"(r) : "f"(x));
    return r;
}
__device__ __forceinline__ void cp16(uint32_t dst, const void* src) {
    asm volatile("cp.async.cg.shared.global [%0], [%1], 16;\n" :: "r"(dst), "l"(src));
}
#define CP_COMMIT() asm volatile("cp.async.commit_group;\n" ::: "memory")

__device__ __forceinline__ void ldsm4(uint32_t& r0, uint32_t& r1, uint32_t& r2, uint32_t& r3,
                                      uint32_t addr) {
    asm volatile("ldmatrix.sync.aligned.m8n8.x4.shared.b16 {%0,%1,%2,%3}, [%4];"
                 : "=r"(r0), "=r"(r1), "=r"(r2), "=r"(r3) : "r"(addr));
}
__device__ __forceinline__ void ldsm4t(uint32_t& r0, uint32_t& r1, uint32_t& r2, uint32_t& r3,
                                       uint32_t addr) {
    asm volatile("ldmatrix.sync.aligned.m8n8.x4.trans.shared.b16 {%0,%1,%2,%3}, [%4];"
                 : "=r"(r0), "=r"(r1), "=r"(r2), "=r"(r3) : "r"(addr));
}
__device__ __forceinline__ void mma16816(float* c, const uint32_t* a, const uint32_t* b) {
    asm volatile(
        "mma.sync.aligned.m16n8k16.row.col.f32.bf16.bf16.f32 "
        "{%0,%1,%2,%3}, {%4,%5,%6,%7}, {%8,%9}, {%0,%1,%2,%3};"
        : "+f"(c[0]), "+f"(c[1]), "+f"(c[2]), "+f"(c[3])
        : "r"(a[0]), "r"(a[1]), "r"(a[2]), "r"(a[3]), "r"(b[0]), "r"(b[1]));
}
__device__ __forceinline__ void mma16816h(float* c, const uint32_t* a, const uint32_t* b) {
    asm volatile(
        "mma.sync.aligned.m16n8k16.row.col.f32.f16.f16.f32 "
        "{%0,%1,%2,%3}, {%4,%5,%6,%7}, {%8,%9}, {%0,%1,%2,%3};"
        : "+f"(c[0]), "+f"(c[1]), "+f"(c[2]), "+f"(c[3])
        : "r"(a[0]), "r"(a[1]), "r"(a[2]), "r"(a[3]), "r"(b[0]), "r"(b[1]));
}
__device__ __forceinline__ uint32_t pkbf(float lo, float hi) {
    uint32_t r;
    asm("cvt.rn.bf16x2.f32 %0, %1, %2;" : "=r"(r) : "f"(hi), "f"(lo));
    return r;
}
__device__ __forceinline__ uint32_t pkhf(float lo, float hi) {
    uint32_t r;
    asm("cvt.rn.f16x2.f32 %0, %1, %2;" : "=r"(r) : "f"(hi), "f"(lo));
    return r;
}
__device__ __forceinline__ void bfsplit(float a, float b, uint32_t& hi, uint32_t& lo) {
    hi = pkbf(a, b);
    float f0 = __uint_as_float(hi << 16);
    float f1 = __uint_as_float(hi & 0xffff0000u);
    lo = pkbf(a - f0, b - f1);
}

// ---------------------------------------------------------------------------
// mega prep: [0,4096) conv x->fp16; [4096,7168) transpose w_attn;
// [7168,8192) transpose w_proj.
// ---------------------------------------------------------------------------
__global__ __launch_bounds__(256) void prep_kernel(
    const float* __restrict__ x,
    const float* __restrict__ w_attn,
    const float* __restrict__ w_proj)
{
    __shared__ float tile[32][33];
    int bid = blockIdx.x;
    int tid = threadIdx.x;
    if (bid < 4096) {
        int i = bid * 256 + tid;
        float4 a = ((const float4*)x)[i];
        ((uint2*)gA_hi)[i] = make_uint2(pkhf(a.x, a.y), pkhf(a.z, a.w));
        return;
    }
    const float* W;
    __half* Th;
    int Nd, bx, by;
    if (bid < 7168) {
        int t = bid - 4096;
        W = w_attn; Th = gBT_hi; Nd = 3072;
        bx = t % 96; by = t / 96;
    } else {
        int t = bid - 7168;
        W = w_proj; Th = gBT2; Nd = 1024;
        bx = t % 32; by = t / 32;
    }
    int nx = bx * 32, kx = by * 32;
    int tx = tid & 31, ty = tid >> 5;
#pragma unroll
    for (int r = ty; r < 32; r += 8)
        tile[r][tx] = W[(size_t)(kx + r) * Nd + nx + tx];
    __syncthreads();
#pragma unroll
    for (int r = ty; r < 32; r += 8) {
        size_t o = (size_t)(nx + r) * 1024 + kx + tx;
        Th[o] = __float2half_rn(tile[tx][r]);
    }
}

// ---------------------------------------------------------------------------
// fp16 single-term mma.sync GEMM: CTA 128x128, warp tile 64x32 (2x4 warps),
// BK=64, cp.async double buffer, 64 KB smem.
// ---------------------------------------------------------------------------
#define G_BHI 16384
#define G_STG 32768
#define TCG_SMEM (2*G_STG)   // 64 KB

__device__ __forceinline__ void load_stage(
    uint32_t sbase,
    const __half* __restrict__ Ah, const __half* __restrict__ Bh,
    int m0, int n0, int k0, int tid)
{
#pragma unroll
    for (int j = 0; j < 4; j++) {
        int idx = tid + j * 256;
        int row = idx >> 3, c = idx & 7;
        uint32_t sw = row * 128 + ((c ^ (row & 7)) << 4);
        size_t ga = (size_t)(m0 + row) * 1024 + k0 + c * 8;
        cp16(sbase + sw, Ah + ga);
    }
#pragma unroll
    for (int j = 0; j < 4; j++) {
        int idx = tid + j * 256;
        int row = idx >> 3, c = idx & 7;
        uint32_t sw = row * 128 + ((c ^ (row & 7)) << 4);
        size_t gb = (size_t)(n0 + row) * 1024 + k0 + c * 8;
        cp16(sbase + G_BHI + sw, Bh + gb);
    }
}

template<int MODE>
__global__ __launch_bounds__(256, 2) void tc_gemm(
    const __half* __restrict__ Ah, const __half* __restrict__ Bh,
    const float* __restrict__ bias, float* __restrict__ Cout,
    const float* __restrict__ p_param)
{
    extern __shared__ char smem[];
    uint32_t sb = smem_u32(smem);
    const int tid  = threadIdx.x;
    const int wid  = tid >> 5;
    const int lane = tid & 31;
    const int wm = wid & 1;
    const int wn = wid >> 1;
    const int m0 = blockIdx.y * 128;
    const int n0 = blockIdx.x * 128;

    float acc[4][4][4];
#pragma unroll
    for (int i = 0; i < 4; i++)
#pragma unroll
        for (int j = 0; j < 4; j++)
#pragma unroll
            for (int q = 0; q < 4; q++) acc[i][j][q] = 0.0f;

    load_stage(sb,         Ah, Bh, m0, n0, 0,  tid); CP_COMMIT();
    load_stage(sb + G_STG, Ah, Bh, m0, n0, 64, tid); CP_COMMIT();

    const int a_row = wm * 64 + (lane & 15);
    const int a_c16 = (lane >> 4);
    const int b_row = wn * 32 + ((lane >> 4) << 3) + (lane & 7);
    const int b_cof = ((lane >> 3) & 1);

    for (int it = 0; it < 16; it++) {
        const int s = it & 1;
        const uint32_t sbase = sb + s * G_STG;
        if (it < 15) asm volatile("cp.async.wait_group 1;\n" ::: "memory");
        else         asm volatile("cp.async.wait_group 0;\n" ::: "memory");
        __syncthreads();

#pragma unroll
        for (int ks = 0; ks < 4; ks++) {
            uint32_t ahi[4][4];
#pragma unroll
            for (int mf = 0; mf < 4; mf++) {
                int row = a_row + mf * 16;
                int c16 = ks * 2 + a_c16;
                uint32_t ad = sbase + row * 128 + ((c16 ^ (row & 7)) << 4);
                ldsm4(ahi[mf][0], ahi[mf][1], ahi[mf][2], ahi[mf][3], ad);
            }
#pragma unroll
            for (int nf2 = 0; nf2 < 2; nf2++) {
                int row = b_row + nf2 * 16;
                int c16 = ks * 2 + b_cof;
                uint32_t bd = sbase + G_BHI + row * 128 + ((c16 ^ (row & 7)) << 4);
                uint32_t bh4[4];
                ldsm4(bh4[0], bh4[1], bh4[2], bh4[3], bd);
#pragma unroll
                for (int mf = 0; mf < 4; mf++) {
                    mma16816h(acc[mf][2*nf2],   ahi[mf], bh4);
                    mma16816h(acc[mf][2*nf2+1], ahi[mf], bh4 + 2);
                }
            }
        }
        __syncthreads();
        if (it + 2 < 16) {
            load_stage(sbase, Ah, Bh, m0, n0, (it + 2) * 64, tid);
            CP_COMMIT();
        }
    }

    const int mbase = m0 + wm * 64 + (lane >> 2);
    const int nbase = n0 + wn * 32 + (lane & 3) * 2;
    const int sec = n0 >> 10;
    float pp0[4], pp1[4];
    if (MODE == 1 && sec == 2) {
#pragma unroll
        for (int nf = 0; nf < 4; nf++) {
            int c1 = (nbase + nf * 8) & 1023;
            pp0[nf] = clamp_p(p_param[c1]);
            pp1[nf] = clamp_p(p_param[c1 + 1]);
        }
    }
#pragma unroll
    for (int mf = 0; mf < 4; mf++) {
#pragma unroll
        for (int half = 0; half < 2; half++) {
            int m = mbase + mf * 16 + half * 8;
#pragma unroll
            for (int nf = 0; nf < 4; nf++) {
                int n = nbase + nf * 8;
                float v0 = acc[mf][nf][half*2+0] + bias[n];
                float v1 = acc[mf][nf][half*2+1] + bias[n+1];
                if (MODE == 0) {
                    *(float2*)(Cout + (size_t)m * Cn + n) = make_float2(v0, v1);
                } else {
                    int c1  = n & 1023;
                    int h   = c1 >> 6, dd = c1 & 63;
                    int bq  = m >> 11, t = m & 2047;
                    size_t idx = ((size_t)((bq * Hn + h) * Tn + t)) * 64 + dd;
                    if (sec == 2) {
                        if (pp0[nf] == 1.0f && pp1[nf] == 1.0f) {
                            float w0 = fmaxf(fabsf(v0 + 5.0f), 1e-10f);
                            float w1 = fmaxf(fabsf(v1 + 5.0f), 1e-10f);
                            uint32_t hh, ll;
                            bfsplit(w0, w1, hh, ll);
                            ((uint32_t*)g_Vh)[idx >> 1] = hh;
                            ((uint32_t*)g_Vl)[idx >> 1] = ll;
                        } else {
                            *(float2*)(g_V + idx) = make_float2(v0, v1);
                        }
                    } else if (sec == 1) {
                        *(uint32_t*)(g_Kh + idx) = pkhf(v0, v1);
                    } else {
                        *(uint32_t*)(g_Qh + idx) = pkhf(v0 * QSCALE, v1 * QSCALE);
                    }
                }
            }
        }
    }
}

// ---------------------------------------------------------------------------
// w-range partial: only for channels with p != 1
// ---------------------------------------------------------------------------
__global__ __launch_bounds__(256) void zmax_part(const float* __restrict__ p_param)
{
    int bh = blockIdx.x, chunk = blockIdx.y;
    int b = bh >> 4, h = bh & 15;
    int d4 = threadIdx.x & 15;
    int g  = threadIdx.x >> 4;
    int c  = h*64 + d4*4;

    bool need = (clamp_p(p_param[c+0]) != 1.0f) || (clamp_p(p_param[c+1]) != 1.0f) ||
                (clamp_p(p_param[c+2]) != 1.0f) || (clamp_p(p_param[c+3]) != 1.0f);

    float4 mx = make_float4(-1e30f, -1e30f, -1e30f, -1e30f);
    float4 mn = make_float4( 1e30f,  1e30f,  1e30f,  1e30f);
    if (need) {
        const float* vp = g_V + (size_t)bh * Tn * 64;
        for (int t = chunk*128 + g; t < (chunk+1)*128; t += 16) {
            float4 v = *(const float4*)(vp + t*64 + d4*4);
            float w0 = fmaxf(fabsf(v.x + 5.0f), 1e-10f);
            float w1 = fmaxf(fabsf(v.y + 5.0f), 1e-10f);
            float w2 = fmaxf(fabsf(v.z + 5.0f), 1e-10f);
            float w3 = fmaxf(fabsf(v.w + 5.0f), 1e-10f);
            mx.x = fmaxf(mx.x, w0); mn.x = fminf(mn.x, w0);
            mx.y = fmaxf(mx.y, w1); mn.y = fminf(mn.y, w1);
            mx.z = fmaxf(mx.z, w2); mn.z = fminf(mn.z, w2);
            mx.w = fmaxf(mx.w, w3); mn.w = fminf(mn.w, w3);
        }
    }
    __shared__ float4 redx[256];
    __shared__ float4 redn[256];
    redx[threadIdx.x] = mx;
    redn[threadIdx.x] = mn;
    __syncthreads();
    if (threadIdx.x < 16) {
        float4 m = redx[threadIdx.x];
        float4 q = redn[threadIdx.x];
#pragma unroll
        for (int gg = 1; gg < 16; gg++) {
            float4 o = redx[gg*16 + threadIdx.x];
            float4 u = redn[gg*16 + threadIdx.x];
            m.x = fmaxf(m.x, o.x); m.y = fmaxf(m.y, o.y);
            m.z = fmaxf(m.z, o.z); m.w = fmaxf(m.w, o.w);
            q.x = fminf(q.x, u.x); q.y = fminf(q.y, u.y);
            q.z = fminf(q.z, u.z); q.w = fminf(q.w, u.w);
        }
        int off = chunk*(Bn*Cn) + b*Cn + h*64 + threadIdx.x*4;
        *(float4*)(g_zpmax + off) = m;
        *(float4*)(g_zpmin + off) = q;
    }
}

// ---------------------------------------------------------------------------
// V transform fixup + inline zmax reduce: only for p != 1 channels.
// Block 0..7 additionally publish g_zmax for the FA epilogue.
// ---------------------------------------------------------------------------
__device__ __forceinline__ float reduce_zmax(int i, float p) {
    float wmax = -1e30f, wmin = 1e30f;
#pragma unroll
    for (int ch = 0; ch < 16; ch++) {
        wmax = fmaxf(wmax, g_zpmax[ch*(Bn*Cn) + i]);
        wmin = fminf(wmin, g_zpmin[ch*(Bn*Cn) + i]);
    }
    return (p >= 0.0f) ? p * __logf(wmax) : p * __logf(wmin);
}

__global__ __launch_bounds__(256) void vexp_kernel(const float* __restrict__ p_param)
{
    int i = blockIdx.x * 256 + threadIdx.x;
    int base = i * 4;
    int dd = base & 63;
    int bh = base >> 17;
    int h = bh & 15, b = bh >> 4;
    int c = h*64 + dd;
    float p0 = clamp_p(p_param[c+0]), p1 = clamp_p(p_param[c+1]);
    float p2 = clamp_p(p_param[c+2]), p3 = clamp_p(p_param[c+3]);
    bool f01 = (p0 == 1.0f) && (p1 == 1.0f);
    bool f23 = (p2 == 1.0f) && (p3 == 1.0f);
    if (blockIdx.x < 8) {
        int gi = blockIdx.x * 256 + threadIdx.x;
        float pg = clamp_p(p_param[gi & (Cn-1)]);
        g_zmax[gi] = (pg == 1.0f) ? 0.0f : reduce_zmax(gi, pg);
    }
    if (f01 && f23) return;
    if (!f01) {
        float zm0 = (p0 == 1.0f) ? 0.0f : reduce_zmax(b*Cn + c,     p0);
        float zm1 = (p1 == 1.0f) ? 0.0f : reduce_zmax(b*Cn + c + 1, p1);
        float2 v = *(const float2*)(g_V + base);
        float w0 = fmaxf(fabsf(v.x + 5.0f), 1e-10f);
        float w1 = fmaxf(fabsf(v.y + 5.0f), 1e-10f);
        float e0 = (p0 == 1.0f) ? w0 : __expf(p0 * __logf(w0) - zm0);
        float e1 = (p1 == 1.0f) ? w1 : __expf(p1 * __logf(w1) - zm1);
        uint32_t hh, ll;
        bfsplit(e0, e1, hh, ll);
        ((uint32_t*)g_Vh)[base >> 1] = hh;
        ((uint32_t*)g_Vl)[base >> 1] = ll;
    }
    if (!f23) {
        float zm2 = (p2 == 1.0f) ? 0.0f : reduce_zmax(b*Cn + c + 2, p2);
        float zm3 = (p3 == 1.0f) ? 0.0f : reduce_zmax(b*Cn + c + 3, p3);
        float2 v = *(const float2*)(g_V + base + 2);
        float w0 = fmaxf(fabsf(v.x + 5.0f), 1e-10f);
        float w1 = fmaxf(fabsf(v.y + 5.0f), 1e-10f);
        float e0 = (p2 == 1.0f) ? w0 : __expf(p2 * __logf(w0) - zm2);
        float e1 = (p3 == 1.0f) ? w1 : __expf(p3 * __logf(w1) - zm3);
        uint32_t hh, ll;
        bfsplit(e0, e1, hh, ll);
        ((uint32_t*)g_Vh)[(base + 2) >> 1] = hh;
        ((uint32_t*)g_Vl)[(base + 2) >> 1] = ll;
    }
}

// ---------------------------------------------------------------------------
// Tensor-core flash attention (causal), BQ=BK=64, 4 warps, 56 KB smem,
// 3 CTAs/SM. S in log2 domain (Q pre-scaled by 0.125*log2e), ex2.approx
// softmax. S = fp16 1-term Qh·Kh; P·V bf16 3-term. p==1: y = mean - 5.
// ---------------------------------------------------------------------------
#define FAQ_H 0
#define FASTG0 8192
#define FASTG_SZ 24576
#define FKH 0
#define FVH 8192
#define FVL 16384
#define FA_SMEM (8192 + 2*FASTG_SZ)   // 56 KB

__device__ __forceinline__ void fa_load_stage(uint32_t sbase, int bh, int kt, int tid)
{
    const char* srcs[3] = {(const char*)g_Kh, (const char*)g_Vh, (const char*)g_Vl};
#pragma unroll
    for (int j = 0; j < 12; j++) {
        int idx = tid + j * 128;
        int arr = idx >> 9;
        int rem = idx & 511;
        int row = rem >> 3, c = rem & 7;
        uint32_t sw = arr * 8192 + row * 128 + ((c ^ (row & 7)) << 4);
        size_t gb = (((size_t)bh * Tn + kt * 64 + row) * 64 + c * 8) * 2;
        cp16(sbase + sw, srcs[arr] + gb);
    }
}

__global__ __launch_bounds__(128, 3) void fa_kernel(const float* __restrict__ p_param)
{
    extern __shared__ char smem[];
    uint32_t sb = smem_u32(smem);
    const int tid  = threadIdx.x;
    const int w    = tid >> 5;
    const int lane = tid & 31;
    const int quad = lane >> 2;
    const int idq  = lane & 3;
    const int bh = blockIdx.y;
    const int b = bh >> 4, h = bh & 15;
    const int qt = (int)gridDim.x - 1 - (int)blockIdx.x;
    const int q0 = qt * 64;

    {
#pragma unroll
        for (int j = 0; j < 4; j++) {
            int idx = tid + j * 128;
            int row = idx >> 3, c = idx & 7;
            uint32_t sw = row * 128 + ((c ^ (row & 7)) << 4);
            size_t gb = (((size_t)bh * Tn + q0 + row) * 64 + c * 8) * 2;
            cp16(sb + FAQ_H + sw, (const char*)g_Qh + gb);
        }
        fa_load_stage(sb + FASTG0, bh, 0, tid);
        CP_COMMIT();
        if (qt >= 1) fa_load_stage(sb + FASTG0 + FASTG_SZ, bh, 1, tid);
        CP_COMMIT();
    }

    uint32_t Qh[4][4];
    float Of[8][4];
    float m0 = -1e30f, m1 = -1e30f, l0 = 0.0f, l1 = 0.0f;
#pragma unroll
    for (int nf = 0; nf < 8; nf++)
#pragma unroll
        for (int q = 0; q < 4; q++) Of[nf][q] = 0.0f;

    const int k_row = ((lane >> 4) << 3) + (lane & 7);
    const int k_cof = ((lane >> 3) & 1);
    const int v_row = (lane & 15);
    const int v_cof = (lane >> 4);

    for (int kt = 0; kt <= qt; kt++) {
        const uint32_t sbase = sb + FASTG0 + (kt & 1) * FASTG_SZ;
        if (kt < qt) asm volatile("cp.async.wait_group 1;\n" ::: "memory");
        else         asm volatile("cp.async.wait_group 0;\n" ::: "memory");
        __syncthreads();

        if (kt == 0) {
            int row = w * 16 + (lane & 15);
#pragma unroll
            for (int ks = 0; ks < 4; ks++) {
                int c16 = ks * 2 + (lane >> 4);
                uint32_t sw = row * 128 + ((c16 ^ (row & 7)) << 4);
                ldsm4(Qh[ks][0], Qh[ks][1], Qh[ks][2], Qh[ks][3], sb + FAQ_H + sw);
            }
        }

        // ---- S = Qh Kh^T  (fp16, 1 term; log2 domain) ----
        float Sf[8][4];
#pragma unroll
        for (int nf = 0; nf < 8; nf++)
#pragma unroll
            for (int q = 0; q < 4; q++) Sf[nf][q] = 0.0f;

#pragma unroll
        for (int nf2 = 0; nf2 < 4; nf2++) {
            int krow = nf2 * 16 + k_row;
#pragma unroll
            for (int ks = 0; ks < 4; ks++) {
                int c16 = ks * 2 + k_cof;
                uint32_t sw = krow * 128 + ((c16 ^ (krow & 7)) << 4);
                uint32_t kh[4];
                ldsm4(kh[0], kh[1], kh[2], kh[3], sbase + FKH + sw);
                mma16816h(Sf[2*nf2],   Qh[ks], kh);
                mma16816h(Sf[2*nf2+1], Qh[ks], kh + 2);
            }
        }

        if (kt == qt) {
            int r0 = w * 16 + quad, r1 = r0 + 8;
#pragma unroll
            for (int nf = 0; nf < 8; nf++) {
                int c0 = nf * 8 + idq * 2;
                if (c0     > r0) Sf[nf][0] = -1e30f;
                if (c0 + 1 > r0) Sf[nf][1] = -1e30f;
                if (c0     > r1) Sf[nf][2] = -1e30f;
                if (c0 + 1 > r1) Sf[nf][3] = -1e30f;
            }
        }

        // ---- softmax in log2 domain (raw ex2.approx MUFU) ----
        float mx0 = -1e30f, mx1 = -1e30f;
#pragma unroll
        for (int nf = 0; nf < 8; nf++) {
            mx0 = fmaxf(mx0, fmaxf(Sf[nf][0], Sf[nf][1]));
            mx1 = fmaxf(mx1, fmaxf(Sf[nf][2], Sf[nf][3]));
        }
#pragma unroll
        for (int off = 1; off < 4; off <<= 1) {
            mx0 = fmaxf(mx0, __shfl_xor_sync(0xffffffffu, mx0, off));
            mx1 = fmaxf(mx1, __shfl_xor_sync(0xffffffffu, mx1, off));
        }
        mx0 = fmaxf(mx0, m0);
        mx1 = fmaxf(mx1, m1);
        float a0 = ex2(m0 - mx0), a1 = ex2(m1 - mx1);
        m0 = mx0; m1 = mx1;

        float s0 = 0.0f, s1 = 0.0f;
#pragma unroll
        for (int nf = 0; nf < 8; nf++) {
            Sf[nf][0] = ex2(Sf[nf][0] - mx0);
            Sf[nf][1] = ex2(Sf[nf][1] - mx0);
            Sf[nf][2] = ex2(Sf[nf][2] - mx1);
            Sf[nf][3] = ex2(Sf[nf][3] - mx1);
            s0 += Sf[nf][0] + Sf[nf][1];
            s1 += Sf[nf][2] + Sf[nf][3];
        }
#pragma unroll
        for (int off = 1; off < 4; off <<= 1) {
            s0 += __shfl_xor_sync(0xffffffffu, s0, off);
            s1 += __shfl_xor_sync(0xffffffffu, s1, off);
        }
        l0 = l0 * a0 + s0;
        l1 = l1 * a1 + s1;

#pragma unroll
        for (int nf = 0; nf < 8; nf++) {
            Of[nf][0] *= a0; Of[nf][1] *= a0;
            Of[nf][2] *= a1; Of[nf][3] *= a1;
        }

        // ---- O += P V (P from S frags, bf16x3, ldsm4t V) ----
#pragma unroll
        for (int kf = 0; kf < 4; kf++) {
            uint32_t pha[4], pla[4];
#pragma unroll
            for (int half = 0; half < 2; half++) {
                float* sp = Sf[2*kf + half];
                bfsplit(sp[0], sp[1], pha[half*2+0], pla[half*2+0]);
                bfsplit(sp[2], sp[3], pha[half*2+1], pla[half*2+1]);
            }
            int vrow = kf * 16 + v_row;
#pragma unroll
            for (int nf2 = 0; nf2 < 4; nf2++) {
                int c16 = nf2 * 2 + v_cof;
                uint32_t sw = vrow * 128 + ((c16 ^ (vrow & 7)) << 4);
                uint32_t vh[4], vl[4];
                ldsm4t(vh[0], vh[1], vh[2], vh[3], sbase + FVH + sw);
                ldsm4t(vl[0], vl[1], vl[2], vl[3], sbase + FVL + sw);
                mma16816(Of[2*nf2],   pha, vh);
                mma16816(Of[2*nf2],   pla, vh);
                mma16816(Of[2*nf2],   pha, vl);
                mma16816(Of[2*nf2+1], pha, vh + 2);
                mma16816(Of[2*nf2+1], pla, vh + 2);
                mma16816(Of[2*nf2+1], pha, vl + 2);
            }
        }

        __syncthreads();
        if (kt + 2 <= qt) {
            fa_load_stage(sbase, bh, kt + 2, tid);
            CP_COMMIT();
        }
    }

    // ---- epilogue: p==1: y = mean - 5; else general ----
    const int t0 = q0 + w * 16 + quad;
    const int t1 = t0 + 8;
    float linv0 = 1.0f / l0, linv1 = 1.0f / l1;
#pragma unroll
    for (int nf = 0; nf < 8; nf++) {
        int d0 = nf * 8 + idq * 2;
        int cg = h * 64 + d0;
        float pv0 = clamp_p(p_param[cg]);
        float pv1 = clamp_p(p_param[cg + 1]);
        float me00 = Of[nf][0] * linv0, me01 = Of[nf][1] * linv0;
        float me10 = Of[nf][2] * linv1, me11 = Of[nf][3] * linv1;
        float y00, y01, y10, y11;
        if (pv0 == 1.0f) {
            y00 = me00 - 5.0f;
            y10 = me10 - 5.0f;
        } else {
            float zm0 = g_zmax[b*Cn + cg];
            y00 = __expf((zm0 + __logf(me00)) / pv0) - 5.0f;
            y10 = __expf((zm0 + __logf(me10)) / pv0) - 5.0f;
        }
        if (pv1 == 1.0f) {
            y01 = me01 - 5.0f;
            y11 = me11 - 5.0f;
        } else {
            float zm1 = g_zmax[b*Cn + cg + 1];
            y01 = __expf((zm1 + __logf(me01)) / pv1) - 5.0f;
            y11 = __expf((zm1 + __logf(me11)) / pv1) - 5.0f;
        }
        size_t i0 = ((size_t)(b*Tn + t0)*Cn + cg) >> 1;
        size_t i1 = ((size_t)(b*Tn + t1)*Cn + cg) >> 1;
        ((uint32_t*)gA_hi)[i0] = pkhf(y00, y01);
        ((uint32_t*)gA_hi)[i1] = pkhf(y10, y11);
    }
}

// ---------------------------------------------------------------------------

extern "C" void kernel_launch(void* const* d_in, const int* in_sizes, int n_in,
                              void* d_out, int out_size)
{
    const float* x       = (const float*)d_in[0];
    const float* w_attn  = (const float*)d_in[1];
    const float* b_attn  = (const float*)d_in[2];
    const float* w_proj  = (const float*)d_in[3];
    const float* b_proj  = (const float*)d_in[4];
    const float* p_param = (const float*)d_in[5];
    float* out = (float*)d_out;

    void *ah, *bth, *bt2;
    cudaGetSymbolAddress(&ah,  gA_hi);
    cudaGetSymbolAddress(&bth, gBT_hi);
    cudaGetSymbolAddress(&bt2, gBT2);

    cudaFuncSetAttribute(fa_kernel, cudaFuncAttributeMaxDynamicSharedMemorySize, FA_SMEM);
    cudaFuncSetAttribute(tc_gemm<0>, cudaFuncAttributeMaxDynamicSharedMemorySize, TCG_SMEM);
    cudaFuncSetAttribute(tc_gemm<1>, cudaFuncAttributeMaxDynamicSharedMemorySize, TCG_SMEM);

    // 1) mega prep: conv x -> fp16, transpose w_attn, transpose w_proj
    prep_kernel<<<8192, 256>>>(x, w_attn, w_proj);

    // 2) QKV GEMM + scatter; V transform fused for p==1 channels
    tc_gemm<1><<<dim3(3072/128, Mn/128), 256, TCG_SMEM>>>(
        (const __half*)ah, (const __half*)bth, b_attn, nullptr, p_param);

    // 3) w-range partials (p!=1 only) + fused reduce/V-fixup
    zmax_part<<<dim3(BHn, 16), 256>>>(p_param);
    vexp_kernel<<<(BHn*Tn*Dn)/1024, 256>>>(p_param);

    // 4) tensor-core causal FA (3 CTAs/SM, ex2.approx log2-domain softmax)
    fa_kernel<<<dim3(Tn/64, BHn), 128, FA_SMEM>>>(p_param);

    // 5) proj GEMM (fp16 single-term)
    tc_gemm<0><<<dim3(Cn/128, Mn/128), 256, TCG_SMEM>>>(
        (const __half*)ah, (const __half*)bt2, b_proj, out, nullptr);
}